// round 14
// baseline (speedup 1.0000x reference)
#include <cuda_runtime.h>
#include <cstdint>

// Problem constants
#define BSZ     8
#define KDIM    4096
#define NDIM    11008
#define RPW     4                        // rows per warp task
#define SPLITK  4
#define KCH     (KDIM / SPLITK)          // 1024 floats per K-chunk
#define KITERS  (KCH / 128)              // 8 iterations (128 floats/row/iter)
#define WARPS_PER_CTA 16
#define THREADS (WARPS_PER_CTA * 32)     // 512
#define CTAS_PER_KC 37
#define NCTAS   (CTAS_PER_KC * SPLITK)   // 148
#define WARPS_PER_KC (CTAS_PER_KC * WARPS_PER_CTA)   // 592
#define NROWGROUPS (NDIM / RPW)          // 2752
#define SMEM_BYTES (BSZ * KCH * 4)       // 32768

// Split-K partial sums: [SPLITK][BSZ][NDIM]
__device__ float g_partial[SPLITK * BSZ * NDIM];
// grid-barrier counters (zero at load; restored to 0 every run)
__device__ int g_arrive;
__device__ int g_done;

typedef unsigned long long ull;

// ---- packed f32x2 FMA (Blackwell f32x2 pipe) ----
__device__ __forceinline__ void ffma2(ull& d, ull a, ull b) {
    asm("fma.rn.f32x2 %0, %1, %2, %0;" : "+l"(d) : "l"(a), "l"(b));
}
__device__ __forceinline__ float sum2(ull a) {
    float lo, hi;
    asm("mov.b64 {%0, %1}, %2;" : "=f"(lo), "=f"(hi) : "l"(a));
    return lo + hi;
}
// streaming 128-bit global load as two packed f32x2 words (bypass L1 reuse)
__device__ __forceinline__ void ldg_cs_v2u64(const void* p, ull& a, ull& b) {
    asm("ld.global.cs.v2.u64 {%0, %1}, [%2];"
        : "=l"(a), "=l"(b) : "l"(p));
}
__device__ __forceinline__ int ldg_cg_s32(const int* p) {
    int v;
    asm volatile("ld.global.cg.s32 %0, [%1];" : "=r"(v) : "l"(p));
    return v;
}
__device__ __forceinline__ float4 ldg_cg_f4(const float* p) {
    float4 v;
    asm volatile("ld.global.cg.v4.f32 {%0, %1, %2, %3}, [%4];"
        : "=f"(v.x), "=f"(v.y), "=f"(v.z), "=f"(v.w) : "l"(p));
    return v;
}

extern __shared__ float xs[];   // [BSZ][KCH] this CTA's x chunk

__global__ __launch_bounds__(THREADS, 1)
void asl_gemv_kernel(const float* __restrict__ x,
                     const float* __restrict__ w,
                     float* __restrict__ out) {
    const int kc        = blockIdx.x & 3;        // fixed K-chunk per CTA
    const int cta_in_kc = blockIdx.x >> 2;       // 0..36
    const int kbase     = kc * KCH;

    // ---- stage this kc's x chunk (8 x 1024 floats = 32 KB) ----
    {
        const float4* x4  = reinterpret_cast<const float4*>(x);
        float4*       xs4 = reinterpret_cast<float4*>(xs);
        #pragma unroll 4
        for (int i = threadIdx.x; i < BSZ * KCH / 4; i += THREADS) {
            const int b = i >> 8;                // / (KCH/4)
            const int o = i & 255;
            xs4[i] = x4[b * (KDIM / 4) + (kbase >> 2) + o];
        }
    }
    __syncthreads();

    const int lane = threadIdx.x & 31;
    const int wid  = threadIdx.x >> 5;
    const ulonglong2* xs2 = reinterpret_cast<const ulonglong2*>(xs);

    for (int rg = cta_in_kc * WARPS_PER_CTA + wid; rg < NROWGROUPS;
         rg += WARPS_PER_KC) {
        const int n0 = rg * RPW;
        const char* wr = reinterpret_cast<const char*>(
            w + (size_t)n0 * KDIM + kbase);

        ull acc[RPW][BSZ];
        #pragma unroll
        for (int r = 0; r < RPW; r++)
            #pragma unroll
            for (int b = 0; b < BSZ; b++)
                acc[r][b] = 0ULL;

        // ---- explicit depth-1 software pipeline on the weight LDGs ----
        ull wc[RPW][2], wn[RPW][2];
        {
            const int koff = lane * 16;
            #pragma unroll
            for (int r = 0; r < RPW; r++)
                ldg_cs_v2u64(wr + (size_t)r * KDIM * 4 + koff,
                             wc[r][0], wc[r][1]);
        }

        #pragma unroll
        for (int it = 0; it < KITERS; it++) {
            if (it + 1 < KITERS) {
                const int koff = ((it + 1) * 32 + lane) * 16;
                #pragma unroll
                for (int r = 0; r < RPW; r++)
                    ldg_cs_v2u64(wr + (size_t)r * KDIM * 4 + koff,
                                 wn[r][0], wn[r][1]);
            }

            const int xoff = it * 32 + lane;          // 16B-unit offset
            #pragma unroll
            for (int b = 0; b < BSZ; b++) {
                ulonglong2 xv = xs2[b * (KCH / 4) + xoff];
                ffma2(acc[0][b], wc[0][0], xv.x); ffma2(acc[0][b], wc[0][1], xv.y);
                ffma2(acc[1][b], wc[1][0], xv.x); ffma2(acc[1][b], wc[1][1], xv.y);
                ffma2(acc[2][b], wc[2][0], xv.x); ffma2(acc[2][b], wc[2][1], xv.y);
                ffma2(acc[3][b], wc[3][0], xv.x); ffma2(acc[3][b], wc[3][1], xv.y);
            }

            #pragma unroll
            for (int r = 0; r < RPW; r++) {
                wc[r][0] = wn[r][0];
                wc[r][1] = wn[r][1];
            }
        }

        // ---- butterfly: 32 partials across 32 lanes in 31 SHFL ----
        float v[32];
        #pragma unroll
        for (int b = 0; b < BSZ; b++)
            #pragma unroll
            for (int r = 0; r < RPW; r++)
                v[b * RPW + r] = sum2(acc[r][b]);

        #pragma unroll
        for (int s = 16; s >= 1; s >>= 1) {
            const bool hi = (lane & s) != 0;
            #pragma unroll
            for (int j = 0; j < s; j++) {
                float mine  = hi ? v[j + s] : v[j];
                float sent  = hi ? v[j]     : v[j + s];
                float other = __shfl_xor_sync(0xFFFFFFFFu, sent, s);
                v[j] = mine + other;
            }
        }

        // lane l -> g_partial[kc][b = l>>2][n0 + (l&3)]  (fire-and-forget)
        g_partial[((size_t)kc * BSZ + (lane >> 2)) * NDIM + n0 + (lane & 3)]
            = v[0];
    }

    // ==== grid barrier: ONE fence + arrive per CTA, then spin ====
    __syncthreads();
    if (threadIdx.x == 0) {
        __threadfence();
        atomicAdd(&g_arrive, 1);
        while (ldg_cg_s32(&g_arrive) < NCTAS)
            __nanosleep(128);
    }
    __syncthreads();

    // ==== cooperative combine: out = sum over SPLITK partials ====
    {
        const int total4 = BSZ * NDIM / 4;                 // 22016
        const int i = blockIdx.x * THREADS + threadIdx.x;  // 75776 threads
        if (i < total4) {
            const float* p = g_partial;
            float4 a0 = ldg_cg_f4(p + (size_t)4 * i);
            float4 a1 = ldg_cg_f4(p + (size_t)4 * (i +     total4));
            float4 a2 = ldg_cg_f4(p + (size_t)4 * (i + 2 * total4));
            float4 a3 = ldg_cg_f4(p + (size_t)4 * (i + 3 * total4));
            float4 o;
            o.x = (a0.x + a1.x) + (a2.x + a3.x);
            o.y = (a0.y + a1.y) + (a2.y + a3.y);
            o.z = (a0.z + a1.z) + (a2.z + a3.z);
            o.w = (a0.w + a1.w) + (a2.w + a3.w);
            reinterpret_cast<float4*>(out)[i] = o;
        }
    }

    // ==== reset counters for next graph replay (last CTA to finish) ====
    __syncthreads();
    if (threadIdx.x == 0) {
        const int old = atomicAdd(&g_done, 1);
        if (old == NCTAS - 1) {
            g_arrive = 0;
            g_done   = 0;
        }
    }
}

extern "C" void kernel_launch(void* const* d_in, const int* in_sizes, int n_in,
                              void* d_out, int out_size) {
    const float* x = (const float*)d_in[0];
    const float* w = (const float*)d_in[1];
    if (n_in >= 2 && in_sizes[0] == NDIM * KDIM) {   // defensive order fix
        const float* t = x; x = w; w = t;
    }
    float* out = (float*)d_out;

    cudaFuncSetAttribute(asl_gemv_kernel,
                         cudaFuncAttributeMaxDynamicSharedMemorySize,
                         SMEM_BYTES);

    asl_gemv_kernel<<<NCTAS, THREADS, SMEM_BYTES>>>(x, w, out);
}

// round 15
// speedup vs baseline: 3.7181x; 3.7181x over previous
#include <cuda_runtime.h>
#include <cstdint>

// Problem constants
#define BSZ     8
#define KDIM    4096
#define NDIM    11008
#define RPW     4                        // rows per warp task
#define SPLITK  4
#define KCH     (KDIM / SPLITK)          // 1024 floats per K-chunk
#define KITERS  (KCH / 128)              // 8 iterations (128 floats/row/iter)
#define WARPS_PER_CTA 16
#define THREADS (WARPS_PER_CTA * 32)     // 512
#define CTAS_PER_KC 37
#define NCTAS   (CTAS_PER_KC * SPLITK)   // 148
#define WARPS_PER_KC (CTAS_PER_KC * WARPS_PER_CTA)   // 592
#define NROWGROUPS (NDIM / RPW)          // 2752
#define SMEM_BYTES (BSZ * KCH * 4)       // 32768

// Split-K partial sums: [SPLITK][BSZ][NDIM]
__device__ float g_partial[SPLITK * BSZ * NDIM];
// grid-barrier counters (zero at load; restored to 0 every run)
__device__ int g_arrive;
__device__ int g_done;

typedef unsigned long long ull;

// ---- packed f32x2 FMA (Blackwell f32x2 pipe) ----
__device__ __forceinline__ void ffma2(ull& d, ull a, ull b) {
    asm("fma.rn.f32x2 %0, %1, %2, %0;" : "+l"(d) : "l"(a), "l"(b));
}
__device__ __forceinline__ float sum2(ull a) {
    float lo, hi;
    asm("mov.b64 {%0, %1}, %2;" : "=f"(lo), "=f"(hi) : "l"(a));
    return lo + hi;
}
// streaming 128-bit global load as two packed f32x2 words (bypass L1 reuse)
__device__ __forceinline__ void ldg_cs_v2u64(const void* p, ull& a, ull& b) {
    asm("ld.global.cs.v2.u64 {%0, %1}, [%2];"
        : "=l"(a), "=l"(b) : "l"(p));
}
__device__ __forceinline__ int ldg_cg_s32(const int* p) {
    int v;
    asm volatile("ld.global.cg.s32 %0, [%1];" : "=r"(v) : "l"(p));
    return v;
}
__device__ __forceinline__ float4 ldg_cg_f4(const float* p) {
    float4 v;
    asm volatile("ld.global.cg.v4.f32 {%0, %1, %2, %3}, [%4];"
        : "=f"(v.x), "=f"(v.y), "=f"(v.z), "=f"(v.w) : "l"(p));
    return v;
}

extern __shared__ float xs[];   // [BSZ][KCH] this CTA's x chunk

__global__ __launch_bounds__(THREADS, 1)
void asl_gemv_kernel(const float* __restrict__ x,
                     const float* __restrict__ w,
                     float* __restrict__ out) {
    const int kc        = blockIdx.x & 3;        // fixed K-chunk per CTA
    const int cta_in_kc = blockIdx.x >> 2;       // 0..36
    const int kbase     = kc * KCH;

    // ---- stage this kc's x chunk (8 x 1024 floats = 32 KB) ----
    {
        const float4* x4  = reinterpret_cast<const float4*>(x);
        float4*       xs4 = reinterpret_cast<float4*>(xs);
        #pragma unroll 4
        for (int i = threadIdx.x; i < BSZ * KCH / 4; i += THREADS) {
            const int b = i >> 8;                // / (KCH/4)
            const int o = i & 255;
            xs4[i] = x4[b * (KDIM / 4) + (kbase >> 2) + o];
        }
    }
    __syncthreads();

    const int lane = threadIdx.x & 31;
    const int wid  = threadIdx.x >> 5;
    const ulonglong2* xs2 = reinterpret_cast<const ulonglong2*>(xs);

    for (int rg = cta_in_kc * WARPS_PER_CTA + wid; rg < NROWGROUPS;
         rg += WARPS_PER_KC) {
        const int n0 = rg * RPW;
        const char* wr = reinterpret_cast<const char*>(
            w + (size_t)n0 * KDIM + kbase);

        ull acc[RPW][BSZ];
        #pragma unroll
        for (int r = 0; r < RPW; r++)
            #pragma unroll
            for (int b = 0; b < BSZ; b++)
                acc[r][b] = 0ULL;

        // ---- depth-1 software pipeline on the weight LDGs.
        // NOTE: loop MUST stay rolled (unroll 1) — live set is
        // acc(64) + wc(16) + wn(16) + temps ~= 112 regs. Full unroll
        // spills catastrophically (R14: 154us).
        ull wc[RPW][2], wn[RPW][2];
        {
            const int koff = lane * 16;
            #pragma unroll
            for (int r = 0; r < RPW; r++)
                ldg_cs_v2u64(wr + (size_t)r * KDIM * 4 + koff,
                             wc[r][0], wc[r][1]);
        }

        #pragma unroll 1
        for (int it = 0; it < KITERS; it++) {
            if (it + 1 < KITERS) {
                const int koff = ((it + 1) * 32 + lane) * 16;
                #pragma unroll
                for (int r = 0; r < RPW; r++)
                    ldg_cs_v2u64(wr + (size_t)r * KDIM * 4 + koff,
                                 wn[r][0], wn[r][1]);
            }

            const int xoff = it * 32 + lane;          // 16B-unit offset
            #pragma unroll
            for (int b = 0; b < BSZ; b++) {
                ulonglong2 xv = xs2[b * (KCH / 4) + xoff];
                ffma2(acc[0][b], wc[0][0], xv.x); ffma2(acc[0][b], wc[0][1], xv.y);
                ffma2(acc[1][b], wc[1][0], xv.x); ffma2(acc[1][b], wc[1][1], xv.y);
                ffma2(acc[2][b], wc[2][0], xv.x); ffma2(acc[2][b], wc[2][1], xv.y);
                ffma2(acc[3][b], wc[3][0], xv.x); ffma2(acc[3][b], wc[3][1], xv.y);
            }

            #pragma unroll
            for (int r = 0; r < RPW; r++) {
                wc[r][0] = wn[r][0];
                wc[r][1] = wn[r][1];
            }
        }

        // ---- butterfly: 32 partials across 32 lanes in 31 SHFL ----
        float v[32];
        #pragma unroll
        for (int b = 0; b < BSZ; b++)
            #pragma unroll
            for (int r = 0; r < RPW; r++)
                v[b * RPW + r] = sum2(acc[r][b]);

        #pragma unroll
        for (int s = 16; s >= 1; s >>= 1) {
            const bool hi = (lane & s) != 0;
            #pragma unroll
            for (int j = 0; j < s; j++) {
                float mine  = hi ? v[j + s] : v[j];
                float sent  = hi ? v[j]     : v[j + s];
                float other = __shfl_xor_sync(0xFFFFFFFFu, sent, s);
                v[j] = mine + other;
            }
        }

        // lane l -> g_partial[kc][b = l>>2][n0 + (l&3)]  (fire-and-forget)
        g_partial[((size_t)kc * BSZ + (lane >> 2)) * NDIM + n0 + (lane & 3)]
            = v[0];
    }

    // ==== grid barrier: ONE fence + arrive per CTA, then spin ====
    __syncthreads();
    if (threadIdx.x == 0) {
        __threadfence();
        atomicAdd(&g_arrive, 1);
        while (ldg_cg_s32(&g_arrive) < NCTAS)
            __nanosleep(128);
    }
    __syncthreads();

    // ==== cooperative combine: out = sum over SPLITK partials ====
    {
        const int total4 = BSZ * NDIM / 4;                 // 22016
        const int i = blockIdx.x * THREADS + threadIdx.x;  // 75776 threads
        if (i < total4) {
            const float* p = g_partial;
            float4 a0 = ldg_cg_f4(p + (size_t)4 * i);
            float4 a1 = ldg_cg_f4(p + (size_t)4 * (i +     total4));
            float4 a2 = ldg_cg_f4(p + (size_t)4 * (i + 2 * total4));
            float4 a3 = ldg_cg_f4(p + (size_t)4 * (i + 3 * total4));
            float4 o;
            o.x = (a0.x + a1.x) + (a2.x + a3.x);
            o.y = (a0.y + a1.y) + (a2.y + a3.y);
            o.z = (a0.z + a1.z) + (a2.z + a3.z);
            o.w = (a0.w + a1.w) + (a2.w + a3.w);
            reinterpret_cast<float4*>(out)[i] = o;
        }
    }

    // ==== reset counters for next graph replay (last CTA to finish) ====
    __syncthreads();
    if (threadIdx.x == 0) {
        const int old = atomicAdd(&g_done, 1);
        if (old == NCTAS - 1) {
            g_arrive = 0;
            g_done   = 0;
        }
    }
}

extern "C" void kernel_launch(void* const* d_in, const int* in_sizes, int n_in,
                              void* d_out, int out_size) {
    const float* x = (const float*)d_in[0];
    const float* w = (const float*)d_in[1];
    if (n_in >= 2 && in_sizes[0] == NDIM * KDIM) {   // defensive order fix
        const float* t = x; x = w; w = t;
    }
    float* out = (float*)d_out;

    cudaFuncSetAttribute(asl_gemv_kernel,
                         cudaFuncAttributeMaxDynamicSharedMemorySize,
                         SMEM_BYTES);

    asl_gemv_kernel<<<NCTAS, THREADS, SMEM_BYTES>>>(x, w, out);
}

// round 16
// speedup vs baseline: 4.1224x; 1.1087x over previous
#include <cuda_runtime.h>
#include <cstdint>

// Problem constants
#define BSZ     8
#define KDIM    4096
#define NDIM    11008
#define RPW     4                        // rows per warp task
#define SPLITK  4
#define KCH     (KDIM / SPLITK)          // 1024 floats per K-chunk
#define KITERS  (KCH / 128)              // 8 iterations (128 floats/row/iter)
#define WARPS_PER_CTA 16
#define THREADS (WARPS_PER_CTA * 32)     // 512
#define CTAS_PER_KC 37
#define NCTAS   (CTAS_PER_KC * SPLITK)   // 148
#define WARPS_PER_KC (CTAS_PER_KC * WARPS_PER_CTA)   // 592
#define NROWGROUPS (NDIM / RPW)          // 2752
#define SMEM_BYTES (BSZ * KCH * 4)       // 32768

// Split-K partial sums: [SPLITK][BSZ][NDIM]
__device__ float g_partial[SPLITK * BSZ * NDIM];
// grid-barrier counters (zero at load; restored to 0 every run)
__device__ int g_arrive;
__device__ int g_done;

typedef unsigned long long ull;

// ---- packed f32x2 FMA (Blackwell f32x2 pipe) ----
__device__ __forceinline__ void ffma2(ull& d, ull a, ull b) {
    asm("fma.rn.f32x2 %0, %1, %2, %0;" : "+l"(d) : "l"(a), "l"(b));
}
__device__ __forceinline__ float sum2(ull a) {
    float lo, hi;
    asm("mov.b64 {%0, %1}, %2;" : "=f"(lo), "=f"(hi) : "l"(a));
    return lo + hi;
}
// streaming 128-bit global load as two packed f32x2 words (bypass L1 reuse)
__device__ __forceinline__ void ldg_cs_v2u64(const void* p, ull& a, ull& b) {
    asm("ld.global.cs.v2.u64 {%0, %1}, [%2];"
        : "=l"(a), "=l"(b) : "l"(p));
}
__device__ __forceinline__ int ldg_cg_s32(const int* p) {
    int v;
    asm volatile("ld.global.cg.s32 %0, [%1];" : "=r"(v) : "l"(p));
    return v;
}
__device__ __forceinline__ float4 ldg_cg_f4(const float* p) {
    float4 v;
    asm volatile("ld.global.cg.v4.f32 {%0, %1, %2, %3}, [%4];"
        : "=f"(v.x), "=f"(v.y), "=f"(v.z), "=f"(v.w) : "l"(p));
    return v;
}

extern __shared__ float xs[];   // [BSZ][KCH] this CTA's x chunk

__global__ __launch_bounds__(THREADS, 1)
void asl_gemv_kernel(const float* __restrict__ x,
                     const float* __restrict__ w,
                     float* __restrict__ out) {
    const int kc        = blockIdx.x & 3;        // fixed K-chunk per CTA
    const int cta_in_kc = blockIdx.x >> 2;       // 0..36
    const int kbase     = kc * KCH;

    // ---- stage this kc's x chunk (8 x 1024 floats = 32 KB) ----
    {
        const float4* x4  = reinterpret_cast<const float4*>(x);
        float4*       xs4 = reinterpret_cast<float4*>(xs);
        #pragma unroll 4
        for (int i = threadIdx.x; i < BSZ * KCH / 4; i += THREADS) {
            const int b = i >> 8;                // / (KCH/4)
            const int o = i & 255;
            xs4[i] = x4[b * (KDIM / 4) + (kbase >> 2) + o];
        }
    }
    __syncthreads();

    const int lane = threadIdx.x & 31;
    const int wid  = threadIdx.x >> 5;
    const ulonglong2* xs2 = reinterpret_cast<const ulonglong2*>(xs);

    for (int rg = cta_in_kc * WARPS_PER_CTA + wid; rg < NROWGROUPS;
         rg += WARPS_PER_KC) {
        const int n0 = rg * RPW;
        const char* wr = reinterpret_cast<const char*>(
            w + (size_t)n0 * KDIM + kbase);

        ull acc[RPW][BSZ];
        #pragma unroll
        for (int r = 0; r < RPW; r++)
            #pragma unroll
            for (int b = 0; b < BSZ; b++)
                acc[r][b] = 0ULL;

        // ---- copy-free two-phase double buffer on the weight LDGs.
        // Even iterations use buffer A, odd use B; each batch is loaded a
        // full iteration before first use. Pair-loop stays ROLLED
        // (unroll 1): live set acc(64)+A(16)+B(16)+temps ~= 112 regs.
        // (R14: full unroll spilled -> 154us. R15: copy-chain variant
        // serialized -> 42us. This version has no copies.)
        ull wa[RPW][2], wb[RPW][2];
        {
            const int koff = lane * 16;
            #pragma unroll
            for (int r = 0; r < RPW; r++)
                ldg_cs_v2u64(wr + (size_t)r * KDIM * 4 + koff,
                             wa[r][0], wa[r][1]);
        }

        #pragma unroll 1
        for (int it = 0; it < KITERS; it += 2) {
            // load odd iteration (it+1) into B
            {
                const int koff = ((it + 1) * 32 + lane) * 16;
                #pragma unroll
                for (int r = 0; r < RPW; r++)
                    ldg_cs_v2u64(wr + (size_t)r * KDIM * 4 + koff,
                                 wb[r][0], wb[r][1]);
            }

            // consume A (iteration it)
            {
                const int xoff = it * 32 + lane;
                #pragma unroll
                for (int b = 0; b < BSZ; b++) {
                    ulonglong2 xv = xs2[b * (KCH / 4) + xoff];
                    ffma2(acc[0][b], wa[0][0], xv.x); ffma2(acc[0][b], wa[0][1], xv.y);
                    ffma2(acc[1][b], wa[1][0], xv.x); ffma2(acc[1][b], wa[1][1], xv.y);
                    ffma2(acc[2][b], wa[2][0], xv.x); ffma2(acc[2][b], wa[2][1], xv.y);
                    ffma2(acc[3][b], wa[3][0], xv.x); ffma2(acc[3][b], wa[3][1], xv.y);
                }
            }

            // load next even iteration (it+2) into A
            if (it + 2 < KITERS) {
                const int koff = ((it + 2) * 32 + lane) * 16;
                #pragma unroll
                for (int r = 0; r < RPW; r++)
                    ldg_cs_v2u64(wr + (size_t)r * KDIM * 4 + koff,
                                 wa[r][0], wa[r][1]);
            }

            // consume B (iteration it+1)
            {
                const int xoff = (it + 1) * 32 + lane;
                #pragma unroll
                for (int b = 0; b < BSZ; b++) {
                    ulonglong2 xv = xs2[b * (KCH / 4) + xoff];
                    ffma2(acc[0][b], wb[0][0], xv.x); ffma2(acc[0][b], wb[0][1], xv.y);
                    ffma2(acc[1][b], wb[1][0], xv.x); ffma2(acc[1][b], wb[1][1], xv.y);
                    ffma2(acc[2][b], wb[2][0], xv.x); ffma2(acc[2][b], wb[2][1], xv.y);
                    ffma2(acc[3][b], wb[3][0], xv.x); ffma2(acc[3][b], wb[3][1], xv.y);
                }
            }
        }

        // ---- butterfly: 32 partials across 32 lanes in 31 SHFL ----
        float v[32];
        #pragma unroll
        for (int b = 0; b < BSZ; b++)
            #pragma unroll
            for (int r = 0; r < RPW; r++)
                v[b * RPW + r] = sum2(acc[r][b]);

        #pragma unroll
        for (int s = 16; s >= 1; s >>= 1) {
            const bool hi = (lane & s) != 0;
            #pragma unroll
            for (int j = 0; j < s; j++) {
                float mine  = hi ? v[j + s] : v[j];
                float sent  = hi ? v[j]     : v[j + s];
                float other = __shfl_xor_sync(0xFFFFFFFFu, sent, s);
                v[j] = mine + other;
            }
        }

        // lane l -> g_partial[kc][b = l>>2][n0 + (l&3)]  (fire-and-forget)
        g_partial[((size_t)kc * BSZ + (lane >> 2)) * NDIM + n0 + (lane & 3)]
            = v[0];
    }

    // ==== grid barrier: ONE fence + arrive per CTA, then spin ====
    __syncthreads();
    if (threadIdx.x == 0) {
        __threadfence();
        atomicAdd(&g_arrive, 1);
        while (ldg_cg_s32(&g_arrive) < NCTAS)
            __nanosleep(128);
    }
    __syncthreads();

    // ==== cooperative combine: out = sum over SPLITK partials ====
    {
        const int total4 = BSZ * NDIM / 4;                 // 22016
        const int i = blockIdx.x * THREADS + threadIdx.x;  // 75776 threads
        if (i < total4) {
            const float* p = g_partial;
            float4 a0 = ldg_cg_f4(p + (size_t)4 * i);
            float4 a1 = ldg_cg_f4(p + (size_t)4 * (i +     total4));
            float4 a2 = ldg_cg_f4(p + (size_t)4 * (i + 2 * total4));
            float4 a3 = ldg_cg_f4(p + (size_t)4 * (i + 3 * total4));
            float4 o;
            o.x = (a0.x + a1.x) + (a2.x + a3.x);
            o.y = (a0.y + a1.y) + (a2.y + a3.y);
            o.z = (a0.z + a1.z) + (a2.z + a3.z);
            o.w = (a0.w + a1.w) + (a2.w + a3.w);
            reinterpret_cast<float4*>(out)[i] = o;
        }
    }

    // ==== reset counters for next graph replay (last CTA to finish) ====
    __syncthreads();
    if (threadIdx.x == 0) {
        const int old = atomicAdd(&g_done, 1);
        if (old == NCTAS - 1) {
            g_arrive = 0;
            g_done   = 0;
        }
    }
}

extern "C" void kernel_launch(void* const* d_in, const int* in_sizes, int n_in,
                              void* d_out, int out_size) {
    const float* x = (const float*)d_in[0];
    const float* w = (const float*)d_in[1];
    if (n_in >= 2 && in_sizes[0] == NDIM * KDIM) {   // defensive order fix
        const float* t = x; x = w; w = t;
    }
    float* out = (float*)d_out;

    cudaFuncSetAttribute(asl_gemv_kernel,
                         cudaFuncAttributeMaxDynamicSharedMemorySize,
                         SMEM_BYTES);

    asl_gemv_kernel<<<NCTAS, THREADS, SMEM_BYTES>>>(x, w, out);
}